// round 9
// baseline (speedup 1.0000x reference)
#include <cuda_runtime.h>
#include <cuda_bf16.h>

// Problem dims (fixed by dataset)
#define BB 4
#define TT_ 512
#define UU 128
#define DD 512
#define VV 512
#define MS (BB * TT_)   // 2048 speech rows
#define MT (BB * UU)    // 512 text rows

// Scratch: projected speech / text (both L2-resident)
__device__ float g_sp[MS * VV];   // speech @ W^T          (4 MB)
__device__ float g_tp[MT * VV];   // text @ W^T + bias     (1 MB)

typedef unsigned long long ull;

// Packed fp32x2 helpers (sm_103a)
#define PACK2(d, s) \
    asm("mov.b64 %0, {%1, %1};" : "=l"(d) : "r"(__float_as_uint(s)))
#define FMA2(acc, a, b) \
    asm("fma.rn.f32x2 %0, %1, %2, %0;" : "+l"(acc) : "l"(a), "l"(b))
#define ADD2(acc, b) \
    asm("add.rn.f32x2 %0, %0, %1;" : "+l"(acc) : "l"(b))

// ---------------------------------------------------------------------------
// Kernel 1: joint GEMM.  C[m, v] = sum_d A[m, d] * W[v, d]  (+bias for text)
// 32x64 tiles, BK=16, 128 threads, grid 640:
//   row-blocks 0..63 = speech -> g_sp; 64..79 = text -> g_tp (+bias).
// 640 CTAs -> ~4.3 CTAs/SM: latency hiding via CTA-level parallelism,
// fine-grained tail (max 5 vs avg 4.3 tiles/SM).
// Per-thread micro-tile 2m x 8v: 8 FFMA2 + 2 PACK + 3 LDS per kk.
// ---------------------------------------------------------------------------
__global__ __launch_bounds__(128)
void joint_gemm_kernel(const float* __restrict__ speech,
                       const float* __restrict__ text,
                       const float* __restrict__ Wm,
                       const float* __restrict__ bias,
                       const int* __restrict__ slen,
                       const int* __restrict__ tlen,
                       float* __restrict__ out)
{
    __shared__ __align__(16) float As[16][36];   // [k][m] 144B rows
    __shared__ __align__(16) float Ws[16][68];   // [k][n] 272B rows

    const int t   = blockIdx.x;          // 0..639
    const int tid = threadIdx.x;
    const int rb  = t >> 3;              // row-block 0..79
    const int v0  = (t & 7) * 64;
    const bool is_text = (rb >= 64);

    const float* A = is_text ? text   + (size_t)(rb - 64) * 32 * DD
                             : speech + (size_t)rb * 32 * DD;
    float* C = is_text ? g_tp + (size_t)(rb - 64) * 32 * VV
                       : g_sp + (size_t)rb * 32 * VV;

    // loaders
    const int alr = tid >> 2;            // A row 0..31
    const int alc = tid & 3;             // k-subchunk
    const int wlr = tid >> 2;            // W rows wlr and wlr+32
    // compute: cols tx*8..+7 (of 64), rows ty*2, ty*2+1 (of 32)
    const int tx = tid & 7;
    const int ty = tid >> 3;

    ull acc[2][4];
#pragma unroll
    for (int i = 0; i < 2; i++)
#pragma unroll
        for (int j = 0; j < 4; j++) acc[i][j] = 0ull;

    const float* Apt = A  + (size_t)alr * DD + alc * 4;
    const float* Wp0 = Wm + (size_t)(v0 + wlr) * DD + alc * 4;
    const float* Wp1 = Wm + (size_t)(v0 + wlr + 32) * DD + alc * 4;

    float4 apre = *(const float4*)Apt;
    float4 wpre0 = *(const float4*)Wp0;
    float4 wpre1 = *(const float4*)Wp1;

    for (int k0 = 0; k0 < DD; k0 += 16) {
        __syncthreads();
        As[alc*4+0][alr] = apre.x; As[alc*4+1][alr] = apre.y;
        As[alc*4+2][alr] = apre.z; As[alc*4+3][alr] = apre.w;
        Ws[alc*4+0][wlr] = wpre0.x; Ws[alc*4+1][wlr] = wpre0.y;
        Ws[alc*4+2][wlr] = wpre0.z; Ws[alc*4+3][wlr] = wpre0.w;
        Ws[alc*4+0][wlr+32] = wpre1.x; Ws[alc*4+1][wlr+32] = wpre1.y;
        Ws[alc*4+2][wlr+32] = wpre1.z; Ws[alc*4+3][wlr+32] = wpre1.w;
        __syncthreads();

        if (k0 + 16 < DD) {
            apre  = *(const float4*)(Apt + k0 + 16);
            wpre0 = *(const float4*)(Wp0 + k0 + 16);
            wpre1 = *(const float4*)(Wp1 + k0 + 16);
        }

#pragma unroll
        for (int kk = 0; kk < 16; kk++) {
            float2 av = *(const float2*)&As[kk][ty * 2];
            ulonglong2 w0 = *(const ulonglong2*)&Ws[kk][tx * 8];
            ulonglong2 w1 = *(const ulonglong2*)&Ws[kk][tx * 8 + 4];
            ull a0, a1;
            PACK2(a0, av.x);
            PACK2(a1, av.y);
            FMA2(acc[0][0], a0, w0.x); FMA2(acc[0][1], a0, w0.y);
            FMA2(acc[0][2], a0, w1.x); FMA2(acc[0][3], a0, w1.y);
            FMA2(acc[1][0], a1, w0.x); FMA2(acc[1][1], a1, w0.y);
            FMA2(acc[1][2], a1, w1.x); FMA2(acc[1][3], a1, w1.y);
        }
    }

    if (is_text) {
        ull b0 = *(const ull*)(bias + v0 + tx * 8);
        ull b1 = *(const ull*)(bias + v0 + tx * 8 + 2);
        ull b2 = *(const ull*)(bias + v0 + tx * 8 + 4);
        ull b3 = *(const ull*)(bias + v0 + tx * 8 + 6);
#pragma unroll
        for (int i = 0; i < 2; i++) {
            ADD2(acc[i][0], b0); ADD2(acc[i][1], b1);
            ADD2(acc[i][2], b2); ADD2(acc[i][3], b3);
        }
    }

#pragma unroll
    for (int i = 0; i < 2; i++) {
        float* cp = C + (size_t)(ty * 2 + i) * VV + v0 + tx * 8;
        ulonglong2 o01, o23;
        o01.x = acc[i][0]; o01.y = acc[i][1];
        o23.x = acc[i][2]; o23.y = acc[i][3];
        *(ulonglong2*)cp       = o01;
        *(ulonglong2*)(cp + 4) = o23;
    }

    // Length tail: outputs 1 and 2 flattened after logits, as float32.
    if (t == 0 && tid < 8) {
        size_t base = (size_t)BB * TT_ * UU * VV;
        if (tid < 4) out[base + tid] = (float)slen[tid];
        else         out[base + tid] = (float)tlen[tid - 4];
    }
}

// ---------------------------------------------------------------------------
// Kernel 2: broadcast add: out[bt, u, v] = sp[bt, v] + tp[b*U + u, v].
// One block per (b,t) row; 128 threads; plain stores (proven 87.7 us).
// ---------------------------------------------------------------------------
__global__ __launch_bounds__(128)
void bcast_add_kernel(float* __restrict__ out)
{
    const int bt  = blockIdx.x;           // 0..2047
    const int b   = bt >> 9;              // bt / T
    const int tid = threadIdx.x;          // 0..127 -> v4 index

    const float4* sp4 = (const float4*)g_sp;
    const float4* tp4 = (const float4*)g_tp;

    float4 s = sp4[(size_t)bt * 128 + tid];

    const float4* tprow = tp4 + (size_t)b * UU * 128 + tid;
    float4* ob = (float4*)out + (size_t)bt * UU * 128 + tid;

#pragma unroll 4
    for (int u = 0; u < UU; u++) {
        float4 t = tprow[(size_t)u * 128];
        float4 r;
        r.x = s.x + t.x;
        r.y = s.y + t.y;
        r.z = s.z + t.z;
        r.w = s.w + t.w;
        ob[(size_t)u * 128] = r;
    }
}

extern "C" void kernel_launch(void* const* d_in, const int* in_sizes, int n_in,
                              void* d_out, int out_size)
{
    const float* speech = (const float*)d_in[0];
    const float* text   = (const float*)d_in[1];
    const float* Wm     = (const float*)d_in[2];
    const float* bias   = (const float*)d_in[3];
    const int*   slen   = (const int*)d_in[4];
    const int*   tlen   = (const int*)d_in[5];

    // Phase 1: both projections (speech + text w/ bias) + length tail
    joint_gemm_kernel<<<640, 128>>>(speech, text, Wm, bias,
                                    slen, tlen, (float*)d_out);

    // Phase 2: broadcast add (DRAM-write-bound floor)
    bcast_add_kernel<<<MS, 128>>>((float*)d_out);
}

// round 10
// speedup vs baseline: 1.3455x; 1.3455x over previous
#include <cuda_runtime.h>
#include <cuda_bf16.h>

// Problem dims (fixed by dataset)
#define BB 4
#define TT_ 512
#define UU 128
#define DD 512
#define VV 512
#define MS (BB * TT_)   // 2048 speech rows
#define MT (BB * UU)    // 512 text rows

// Scratch: projected speech / text (both L2-resident)
__device__ float g_sp[MS * VV];   // speech @ W^T          (4 MB)
__device__ float g_tp[MT * VV];   // text @ W^T + bias     (1 MB)

typedef unsigned long long ull;

// Packed fp32x2 helpers (sm_103a)
#define PACK2(d, s) \
    asm("mov.b64 %0, {%1, %1};" : "=l"(d) : "r"(__float_as_uint(s)))
#define FMA2(acc, a, b) \
    asm("fma.rn.f32x2 %0, %1, %2, %0;" : "+l"(acc) : "l"(a), "l"(b))
#define ADD2(acc, b) \
    asm("add.rn.f32x2 %0, %0, %1;" : "+l"(acc) : "l"(b))

// ---------------------------------------------------------------------------
// Kernel 1: joint GEMM.  C[m, v] = sum_d A[m, d] * W[v, d]  (+bias for text)
// R6 config (best measured): 64x64 tiles, BK=16, 256 threads, grid 320
// (tiles 0..255 speech -> g_sp, 256..319 text -> g_tp with bias).
// NEW vs R6: double-buffered smem (ONE sync per k-chunk) + 3 CTAs/SM.
// Per-thread micro-tile 4m x 4v as 4x2 f32x2 accumulators.
// ---------------------------------------------------------------------------
__global__ __launch_bounds__(256, 3)
void joint_gemm_kernel(const float* __restrict__ speech,
                       const float* __restrict__ text,
                       const float* __restrict__ Wm,
                       const float* __restrict__ bias,
                       const int* __restrict__ slen,
                       const int* __restrict__ tlen,
                       float* __restrict__ out)
{
    __shared__ __align__(16) float As[2][16][68];   // [buf][k][m]
    __shared__ __align__(16) float Ws[2][16][68];   // [buf][k][n]

    const int t   = blockIdx.x;
    const int tid = threadIdx.x;
    const bool is_text = (t >= 256);
    const int mblk = is_text ? ((t - 256) >> 3) : (t >> 3);
    const int v0   = (t & 7) * 64;

    const float* A = is_text ? text   + (size_t)mblk * 64 * DD
                             : speech + (size_t)mblk * 64 * DD;
    float* C = is_text ? g_tp + (size_t)mblk * 64 * VV
                       : g_sp + (size_t)mblk * 64 * VV;

    const int lr = tid >> 2;     // 0..63  load row
    const int lc = tid & 3;      // 0..3   load k-subchunk
    const int tx = tid & 15;     // cols tx*4 .. +3
    const int ty = tid >> 4;     // rows ty*4 .. +3

    ull acc[4][2];
#pragma unroll
    for (int i = 0; i < 4; i++) { acc[i][0] = 0ull; acc[i][1] = 0ull; }

    const float* Arow = A  + (size_t)lr * DD + lc * 4;
    const float* Wrow = Wm + (size_t)(v0 + lr) * DD + lc * 4;

    // Prologue: chunk 0 -> buf 0, prefetch chunk 1 into regs.
    {
        float4 a = *(const float4*)Arow;
        float4 w = *(const float4*)Wrow;
        As[0][lc*4+0][lr] = a.x; As[0][lc*4+1][lr] = a.y;
        As[0][lc*4+2][lr] = a.z; As[0][lc*4+3][lr] = a.w;
        Ws[0][lc*4+0][lr] = w.x; Ws[0][lc*4+1][lr] = w.y;
        Ws[0][lc*4+2][lr] = w.z; Ws[0][lc*4+3][lr] = w.w;
    }
    float4 apre = *(const float4*)(Arow + 16);
    float4 wpre = *(const float4*)(Wrow + 16);
    __syncthreads();

    for (int kc = 0; kc < 32; kc++) {
        const int cur = kc & 1;

        // Store prefetched chunk kc+1 into the free buffer, then issue the
        // gmem loads for chunk kc+2. Safe: the sync at end of kc-1 ensured
        // everyone finished computing on buf cur^1.
        if (kc < 31) {
            const int nxt = cur ^ 1;
            As[nxt][lc*4+0][lr] = apre.x; As[nxt][lc*4+1][lr] = apre.y;
            As[nxt][lc*4+2][lr] = apre.z; As[nxt][lc*4+3][lr] = apre.w;
            Ws[nxt][lc*4+0][lr] = wpre.x; Ws[nxt][lc*4+1][lr] = wpre.y;
            Ws[nxt][lc*4+2][lr] = wpre.z; Ws[nxt][lc*4+3][lr] = wpre.w;
            if (kc < 30) {
                apre = *(const float4*)(Arow + (kc + 2) * 16);
                wpre = *(const float4*)(Wrow + (kc + 2) * 16);
            }
        }

#pragma unroll
        for (int kk = 0; kk < 16; kk++) {
            float4 av = *(const float4*)&As[cur][kk][ty * 4];
            ulonglong2 wv = *(const ulonglong2*)&Ws[cur][kk][tx * 4];
            ull aa;
            PACK2(aa, av.x);
            FMA2(acc[0][0], aa, wv.x); FMA2(acc[0][1], aa, wv.y);
            PACK2(aa, av.y);
            FMA2(acc[1][0], aa, wv.x); FMA2(acc[1][1], aa, wv.y);
            PACK2(aa, av.z);
            FMA2(acc[2][0], aa, wv.x); FMA2(acc[2][1], aa, wv.y);
            PACK2(aa, av.w);
            FMA2(acc[3][0], aa, wv.x); FMA2(acc[3][1], aa, wv.y);
        }
        __syncthreads();
    }

    if (is_text) {
        ull b0 = *(const ull*)(bias + v0 + tx * 4);
        ull b1 = *(const ull*)(bias + v0 + tx * 4 + 2);
#pragma unroll
        for (int i = 0; i < 4; i++) { ADD2(acc[i][0], b0); ADD2(acc[i][1], b1); }
    }

#pragma unroll
    for (int i = 0; i < 4; i++) {
        ulonglong2 o;
        o.x = acc[i][0]; o.y = acc[i][1];
        *(ulonglong2*)(C + (size_t)(ty * 4 + i) * VV + v0 + tx * 4) = o;
    }

    // Length tail: outputs 1 and 2 flattened after logits, as float32.
    if (t == 0 && tid < 8) {
        size_t base = (size_t)BB * TT_ * UU * VV;
        if (tid < 4) out[base + tid] = (float)slen[tid];
        else         out[base + tid] = (float)tlen[tid - 4];
    }
}

// ---------------------------------------------------------------------------
// Kernel 2: broadcast add: out[bt, u, v] = sp[bt, v] + tp[b*U + u, v].
// One block per (b,t) row; 128 threads; plain stores (proven 87.5 us floor).
// ---------------------------------------------------------------------------
__global__ __launch_bounds__(128)
void bcast_add_kernel(float* __restrict__ out)
{
    const int bt  = blockIdx.x;           // 0..2047
    const int b   = bt >> 9;              // bt / T
    const int tid = threadIdx.x;          // 0..127 -> v4 index

    const float4* sp4 = (const float4*)g_sp;
    const float4* tp4 = (const float4*)g_tp;

    float4 s = sp4[(size_t)bt * 128 + tid];

    const float4* tprow = tp4 + (size_t)b * UU * 128 + tid;
    float4* ob = (float4*)out + (size_t)bt * UU * 128 + tid;

#pragma unroll 4
    for (int u = 0; u < UU; u++) {
        float4 t = tprow[(size_t)u * 128];
        float4 r;
        r.x = s.x + t.x;
        r.y = s.y + t.y;
        r.z = s.z + t.z;
        r.w = s.w + t.w;
        ob[(size_t)u * 128] = r;
    }
}

extern "C" void kernel_launch(void* const* d_in, const int* in_sizes, int n_in,
                              void* d_out, int out_size)
{
    const float* speech = (const float*)d_in[0];
    const float* text   = (const float*)d_in[1];
    const float* Wm     = (const float*)d_in[2];
    const float* bias   = (const float*)d_in[3];
    const int*   slen   = (const int*)d_in[4];
    const int*   tlen   = (const int*)d_in[5];

    // Phase 1: both projections (speech + text w/ bias) + length tail
    joint_gemm_kernel<<<320, 256>>>(speech, text, Wm, bias,
                                    slen, tlen, (float*)d_out);

    // Phase 2: broadcast add (DRAM-write-bound floor)
    bcast_add_kernel<<<MS, 128>>>((float*)d_out);
}

// round 11
// speedup vs baseline: 1.5903x; 1.1819x over previous
#include <cuda_runtime.h>
#include <cuda_bf16.h>
#include <cstdint>

// Problem dims (fixed by dataset)
#define BB 4
#define TT_ 512
#define UU 128
#define DD 512
#define VV 512
#define MS (BB * TT_)    // 2048 speech rows
#define MT (BB * UU)     // 512 text rows
#define MA (MS + MT)     // 2560 combined A rows

// Scratch
__device__ float g_sp[MS * VV];   // speech @ W^T          (4 MB)
__device__ float g_tp[MT * VV];   // text @ W^T + bias     (1 MB)
__device__ __align__(16) __nv_bfloat16 g_Ahi[MA * DD];
__device__ __align__(16) __nv_bfloat16 g_Alo[MA * DD];
__device__ __align__(16) __nv_bfloat16 g_Whi[VV * DD];
__device__ __align__(16) __nv_bfloat16 g_Wlo[VV * DD];

__device__ __forceinline__ uint32_t s2u(const void* p) {
    return (uint32_t)__cvta_generic_to_shared(p);
}

#define LDSM4(r0, r1, r2, r3, addr) \
    asm volatile("ldmatrix.sync.aligned.m8n8.x4.shared.b16 {%0,%1,%2,%3}, [%4];" \
                 : "=r"(r0), "=r"(r1), "=r"(r2), "=r"(r3) : "r"(addr))
#define LDSM2(r0, r1, addr) \
    asm volatile("ldmatrix.sync.aligned.m8n8.x2.shared.b16 {%0,%1}, [%2];" \
                 : "=r"(r0), "=r"(r1) : "r"(addr))
#define MMA16816(d, a0, a1, a2, a3, b0, b1) \
    asm volatile("mma.sync.aligned.m16n8k16.row.col.f32.bf16.bf16.f32 " \
                 "{%0,%1,%2,%3},{%4,%5,%6,%7},{%8,%9},{%0,%1,%2,%3};" \
                 : "+f"(d[0]), "+f"(d[1]), "+f"(d[2]), "+f"(d[3]) \
                 : "r"(a0), "r"(a1), "r"(a2), "r"(a3), "r"(b0), "r"(b1))

// ---------------------------------------------------------------------------
// Kernel 0: fp32 -> (bf16 hi, bf16 lo) split of [speech; text] and W.
// 768 blocks x 256 threads x 8 elems = 1,572,864 elements exactly.
// Also writes the float-cast length tail.
// ---------------------------------------------------------------------------
__global__ __launch_bounds__(256)
void convert_kernel(const float* __restrict__ speech,
                    const float* __restrict__ text,
                    const float* __restrict__ Wm,
                    const int* __restrict__ slen,
                    const int* __restrict__ tlen,
                    float* __restrict__ out)
{
    const size_t e = ((size_t)blockIdx.x * 256 + threadIdx.x) * 8;
    const float* src;
    __nv_bfloat16 *dhi, *dlo;
    if (e < (size_t)MS * DD) {
        src = speech + e;               dhi = g_Ahi + e; dlo = g_Alo + e;
    } else if (e < (size_t)MA * DD) {
        src = text + (e - (size_t)MS * DD);
        dhi = g_Ahi + e; dlo = g_Alo + e;
    } else {
        size_t w = e - (size_t)MA * DD;
        src = Wm + w;                   dhi = g_Whi + w; dlo = g_Wlo + w;
    }

    float4 x0 = *(const float4*)src;
    float4 x1 = *(const float4*)(src + 4);
    float xs[8] = {x0.x, x0.y, x0.z, x0.w, x1.x, x1.y, x1.z, x1.w};

    union { __nv_bfloat16 h[8]; uint4 v; } uhi, ulo;
#pragma unroll
    for (int i = 0; i < 8; i++) {
        __nv_bfloat16 h = __float2bfloat16(xs[i]);
        uhi.h[i] = h;
        ulo.h[i] = __float2bfloat16(xs[i] - __bfloat162float(h));
    }
    *(uint4*)dhi = uhi.v;
    *(uint4*)dlo = ulo.v;

    // Length tail: outputs 1 and 2 flattened after logits, as float32.
    if (blockIdx.x == 0 && threadIdx.x < 8) {
        size_t base = (size_t)BB * TT_ * UU * VV;
        int i = threadIdx.x;
        if (i < 4) out[base + i] = (float)slen[i];
        else       out[base + i] = (float)tlen[i - 4];
    }
}

// ---------------------------------------------------------------------------
// Kernel 1: tensor-core split GEMM.  C[m,v] = sum_d A[m,d] * W[v,d] (+bias)
// C = Ahi*Whi + Ahi*Wlo + Alo*Whi, fp32 accum (3x mma.sync m16n8k16 bf16).
// 64x64 tiles, 256 threads (8 warps = 4m x 2n), grid 320 (rb>=32 -> text).
// Double-buffered smem, k-chunk = 32 (2 k16 substeps), one sync per chunk.
// smem rows padded to 80B: ldmatrix banks (20r mod 32) all distinct.
// ---------------------------------------------------------------------------
__global__ __launch_bounds__(256, 3)
void mma_gemm_kernel(const float* __restrict__ bias)
{
    // per buffer: Ahi[64][80B] | Alo | Whi | Wlo  (5120B each, 20480 total)
    __shared__ __align__(16) unsigned char smem[2][20480];

    const int t   = blockIdx.x;     // 0..319
    const int tid = threadIdx.x;
    const int rb  = t >> 3;         // 0..39 (combined row-block)
    const int v0  = (t & 7) * 64;
    const bool is_text = (rb >= 32);
    const int m0 = rb * 64;
    float* C = is_text ? g_tp + (size_t)(rb - 32) * 64 * VV
                       : g_sp + (size_t)rb * 64 * VV;

    // gmem->smem loaders: row ar (0..63), 16B segment ac (0..3)
    const int ar = tid >> 2, ac = tid & 3;
    const __nv_bfloat16* pAhi = g_Ahi + (size_t)(m0 + ar) * DD + ac * 8;
    const __nv_bfloat16* pAlo = g_Alo + (size_t)(m0 + ar) * DD + ac * 8;
    const __nv_bfloat16* pWhi = g_Whi + (size_t)(v0 + ar) * DD + ac * 8;
    const __nv_bfloat16* pWlo = g_Wlo + (size_t)(v0 + ar) * DD + ac * 8;
    const int soff = ar * 80 + ac * 16;

    // warp tile coords
    const int lane = tid & 31;
    const int wrp  = tid >> 5;
    const int wm   = wrp & 3;       // m16 group (0..3)
    const int wn   = wrp >> 2;      // n32 group (0..1)

    // ldmatrix per-lane smem geometry
    const int aRow  = wm * 16 + (lane & 15);
    const int aByte = ((lane >> 4) & 1) * 16;
    const int bRow  = wn * 32 + (lane & 7);          // + j*8
    const int bByte = ((lane >> 3) & 1) * 16;

    float acc[4][4];
#pragma unroll
    for (int j = 0; j < 4; j++)
#pragma unroll
        for (int i = 0; i < 4; i++) acc[j][i] = 0.f;

    // Prologue: chunk 0 -> buf 0; prefetch chunk 1 into regs.
    uint4 rAh = *(const uint4*)pAhi;
    uint4 rAl = *(const uint4*)pAlo;
    uint4 rWh = *(const uint4*)pWhi;
    uint4 rWl = *(const uint4*)pWlo;
    {
        unsigned char* b0 = smem[0];
        *(uint4*)(b0 +         soff) = rAh;
        *(uint4*)(b0 +  5120 + soff) = rAl;
        *(uint4*)(b0 + 10240 + soff) = rWh;
        *(uint4*)(b0 + 15360 + soff) = rWl;
    }
    rAh = *(const uint4*)(pAhi + 32);
    rAl = *(const uint4*)(pAlo + 32);
    rWh = *(const uint4*)(pWhi + 32);
    rWl = *(const uint4*)(pWlo + 32);
    __syncthreads();

    for (int kc = 0; kc < 16; kc++) {
        unsigned char* cb = smem[kc & 1];

        if (kc < 15) {
            unsigned char* nb = smem[(kc & 1) ^ 1];
            *(uint4*)(nb +         soff) = rAh;
            *(uint4*)(nb +  5120 + soff) = rAl;
            *(uint4*)(nb + 10240 + soff) = rWh;
            *(uint4*)(nb + 15360 + soff) = rWl;
            if (kc < 14) {
                const int ko = (kc + 2) * 32;
                rAh = *(const uint4*)(pAhi + ko);
                rAl = *(const uint4*)(pAlo + ko);
                rWh = *(const uint4*)(pWhi + ko);
                rWl = *(const uint4*)(pWlo + ko);
            }
        }

#pragma unroll
        for (int ks = 0; ks < 2; ks++) {
            uint32_t aAddr = s2u(cb + aRow * 80 + ks * 32 + aByte);
            uint32_t ah0, ah1, ah2, ah3, al0, al1, al2, al3;
            LDSM4(ah0, ah1, ah2, ah3, aAddr);
            LDSM4(al0, al1, al2, al3, aAddr + 5120);

#pragma unroll
            for (int j = 0; j < 4; j++) {
                uint32_t bAddr = s2u(cb + 10240 + (bRow + j * 8) * 80
                                        + ks * 32 + bByte);
                uint32_t bh0, bh1, bl0, bl1;
                LDSM2(bh0, bh1, bAddr);
                LDSM2(bl0, bl1, bAddr + 5120);
                MMA16816(acc[j], ah0, ah1, ah2, ah3, bh0, bh1);
                MMA16816(acc[j], ah0, ah1, ah2, ah3, bl0, bl1);
                MMA16816(acc[j], al0, al1, al2, al3, bh0, bh1);
            }
        }
        __syncthreads();
    }

    // Epilogue: D frag -> C rows (row = wm*16 + lane/4 (+8)), cols (lane%4)*2.
    const int erow  = wm * 16 + (lane >> 2);
    const int ecol0 = wn * 32 + (lane & 3) * 2;
#pragma unroll
    for (int j = 0; j < 4; j++) {
        const int col = ecol0 + j * 8;
        float b0v = 0.f, b1v = 0.f;
        if (is_text) { b0v = bias[v0 + col]; b1v = bias[v0 + col + 1]; }
        float2 o0 = make_float2(acc[j][0] + b0v, acc[j][1] + b1v);
        float2 o1 = make_float2(acc[j][2] + b0v, acc[j][3] + b1v);
        *(float2*)(C + (size_t)erow * VV + v0 + col)       = o0;
        *(float2*)(C + (size_t)(erow + 8) * VV + v0 + col) = o1;
    }
}

// ---------------------------------------------------------------------------
// Kernel 2: broadcast add: out[bt, u, v] = sp[bt, v] + tp[b*U + u, v].
// One block per (b,t) row; 128 threads; plain stores (proven ~88 us floor).
// ---------------------------------------------------------------------------
__global__ __launch_bounds__(128)
void bcast_add_kernel(float* __restrict__ out)
{
    const int bt  = blockIdx.x;           // 0..2047
    const int b   = bt >> 9;              // bt / T
    const int tid = threadIdx.x;          // 0..127 -> v4 index

    const float4* sp4 = (const float4*)g_sp;
    const float4* tp4 = (const float4*)g_tp;

    float4 s = sp4[(size_t)bt * 128 + tid];

    const float4* tprow = tp4 + (size_t)b * UU * 128 + tid;
    float4* ob = (float4*)out + (size_t)bt * UU * 128 + tid;

#pragma unroll 4
    for (int u = 0; u < UU; u++) {
        float4 t = tprow[(size_t)u * 128];
        float4 r;
        r.x = s.x + t.x;
        r.y = s.y + t.y;
        r.z = s.z + t.z;
        r.w = s.w + t.w;
        ob[(size_t)u * 128] = r;
    }
}

extern "C" void kernel_launch(void* const* d_in, const int* in_sizes, int n_in,
                              void* d_out, int out_size)
{
    const float* speech = (const float*)d_in[0];
    const float* text   = (const float*)d_in[1];
    const float* Wm     = (const float*)d_in[2];
    const float* bias   = (const float*)d_in[3];
    const int*   slen   = (const int*)d_in[4];
    const int*   tlen   = (const int*)d_in[5];

    // Phase 0: fp32 -> bf16 hi/lo split (+ length tail)
    convert_kernel<<<768, 256>>>(speech, text, Wm, slen, tlen, (float*)d_out);

    // Phase 1: tensor-core split GEMM (speech + text w/ bias)
    mma_gemm_kernel<<<320, 256>>>(bias);

    // Phase 2: broadcast add (DRAM-write-bound floor)
    bcast_add_kernel<<<MS, 128>>>((float*)d_out);
}

// round 12
// speedup vs baseline: 1.5941x; 1.0024x over previous
#include <cuda_runtime.h>
#include <cuda_bf16.h>
#include <cstdint>

// Problem dims (fixed by dataset)
#define BB 4
#define TT_ 512
#define UU 128
#define DD 512
#define VV 512
#define MS (BB * TT_)    // 2048 speech rows
#define MT (BB * UU)     // 512 text rows
#define MA (MS + MT)     // 2560 combined A rows

// Scratch
__device__ float g_sp[MS * VV];   // speech @ W^T          (4 MB)
__device__ float g_tp[MT * VV];   // text @ W^T + bias     (1 MB)
__device__ __align__(16) __nv_bfloat16 g_Ahi[MA * DD];
__device__ __align__(16) __nv_bfloat16 g_Alo[MA * DD];
__device__ __align__(16) __nv_bfloat16 g_Whi[VV * DD];
__device__ __align__(16) __nv_bfloat16 g_Wlo[VV * DD];

__device__ __forceinline__ uint32_t s2u(const void* p) {
    return (uint32_t)__cvta_generic_to_shared(p);
}

#define LDSM4(r0, r1, r2, r3, addr) \
    asm volatile("ldmatrix.sync.aligned.m8n8.x4.shared.b16 {%0,%1,%2,%3}, [%4];" \
                 : "=r"(r0), "=r"(r1), "=r"(r2), "=r"(r3) : "r"(addr))
#define MMA16816(d, a0, a1, a2, a3, b0, b1) \
    asm volatile("mma.sync.aligned.m16n8k16.row.col.f32.bf16.bf16.f32 " \
                 "{%0,%1,%2,%3},{%4,%5,%6,%7},{%8,%9},{%0,%1,%2,%3};" \
                 : "+f"(d[0]), "+f"(d[1]), "+f"(d[2]), "+f"(d[3]) \
                 : "r"(a0), "r"(a1), "r"(a2), "r"(a3), "r"(b0), "r"(b1))

// ---------------------------------------------------------------------------
// Kernel 0: fp32 -> (bf16 hi, bf16 lo) split of [speech; text] and W.
// 768 blocks x 256 threads x 8 elems = 1,572,864 elements exactly.
// Also writes the float-cast length tail.
// ---------------------------------------------------------------------------
__global__ __launch_bounds__(256)
void convert_kernel(const float* __restrict__ speech,
                    const float* __restrict__ text,
                    const float* __restrict__ Wm,
                    const int* __restrict__ slen,
                    const int* __restrict__ tlen,
                    float* __restrict__ out)
{
    const size_t e = ((size_t)blockIdx.x * 256 + threadIdx.x) * 8;
    const float* src;
    __nv_bfloat16 *dhi, *dlo;
    if (e < (size_t)MS * DD) {
        src = speech + e;               dhi = g_Ahi + e; dlo = g_Alo + e;
    } else if (e < (size_t)MA * DD) {
        src = text + (e - (size_t)MS * DD);
        dhi = g_Ahi + e; dlo = g_Alo + e;
    } else {
        size_t w = e - (size_t)MA * DD;
        src = Wm + w;                   dhi = g_Whi + w; dlo = g_Wlo + w;
    }

    float4 x0 = *(const float4*)src;
    float4 x1 = *(const float4*)(src + 4);
    float xs[8] = {x0.x, x0.y, x0.z, x0.w, x1.x, x1.y, x1.z, x1.w};

    union { __nv_bfloat16 h[8]; uint4 v; } uhi, ulo;
#pragma unroll
    for (int i = 0; i < 8; i++) {
        __nv_bfloat16 h = __float2bfloat16(xs[i]);
        uhi.h[i] = h;
        ulo.h[i] = __float2bfloat16(xs[i] - __bfloat162float(h));
    }
    *(uint4*)dhi = uhi.v;
    *(uint4*)dlo = ulo.v;

    // Length tail: outputs 1 and 2 flattened after logits, as float32.
    if (blockIdx.x == 0 && threadIdx.x < 8) {
        size_t base = (size_t)BB * TT_ * UU * VV;
        int i = threadIdx.x;
        if (i < 4) out[base + i] = (float)slen[i];
        else       out[base + i] = (float)tlen[i - 4];
    }
}

// ---------------------------------------------------------------------------
// Kernel 1: tensor-core split GEMM.  C[m,v] = sum_d A[m,d] * W[v,d] (+bias)
// C = Ahi*Whi + Ahi*Wlo + Alo*Whi, fp32 accum (3x mma.sync m16n8k16 bf16).
// 64x64 tiles, 256 threads (8 warps = 4m x 2n), grid 320 (rb>=32 -> text).
// Double-buffered smem, k-chunk = 32, one sync per chunk.
// B-side now uses LDSM4 packing (j0,k0)(j0,k1)(j1,k0)(j1,k1) per instr:
// 6 LDSM per k16-substep (was 10) against 12 HMMA.
// ---------------------------------------------------------------------------
__global__ __launch_bounds__(256, 3)
void mma_gemm_kernel(const float* __restrict__ bias)
{
    // per buffer: Ahi[64][80B] | Alo | Whi | Wlo  (5120B each, 20480 total)
    __shared__ __align__(16) unsigned char smem[2][20480];

    const int t   = blockIdx.x;     // 0..319
    const int tid = threadIdx.x;
    const int rb  = t >> 3;         // 0..39 (combined row-block)
    const int v0  = (t & 7) * 64;
    const bool is_text = (rb >= 32);
    const int m0 = rb * 64;
    float* C = is_text ? g_tp + (size_t)(rb - 32) * 64 * VV
                       : g_sp + (size_t)rb * 64 * VV;

    // gmem->smem loaders: row ar (0..63), 16B segment ac (0..3)
    const int ar = tid >> 2, ac = tid & 3;
    const __nv_bfloat16* pAhi = g_Ahi + (size_t)(m0 + ar) * DD + ac * 8;
    const __nv_bfloat16* pAlo = g_Alo + (size_t)(m0 + ar) * DD + ac * 8;
    const __nv_bfloat16* pWhi = g_Whi + (size_t)(v0 + ar) * DD + ac * 8;
    const __nv_bfloat16* pWlo = g_Wlo + (size_t)(v0 + ar) * DD + ac * 8;
    const int soff = ar * 80 + ac * 16;

    // warp tile coords
    const int lane = tid & 31;
    const int wrp  = tid >> 5;
    const int wm   = wrp & 3;       // m16 group (0..3)
    const int wn   = wrp >> 2;      // n32 group (0..1)

    // A ldmatrix lane geometry (x4: m16 x k16)
    const int aRow  = wm * 16 + (lane & 15);
    const int aByte = ((lane >> 4) & 1) * 16;
    // B ldmatrix lane geometry (x4 packs (j,k-half) quads):
    //   lanes 0-7  -> (j=jp*2,   k 0-7)    lanes 8-15  -> (j=jp*2,   k 8-15)
    //   lanes 16-23-> (j=jp*2+1, k 0-7)    lanes 24-31 -> (j=jp*2+1, k 8-15)
    const int bRow4  = wn * 32 + ((lane >> 4) & 1) * 8 + (lane & 7);
    const int bByte4 = ((lane >> 3) & 1) * 16;

    float acc[4][4];
#pragma unroll
    for (int j = 0; j < 4; j++)
#pragma unroll
        for (int i = 0; i < 4; i++) acc[j][i] = 0.f;

    // Prologue: chunk 0 -> buf 0; prefetch chunk 1 into regs.
    uint4 rAh = *(const uint4*)pAhi;
    uint4 rAl = *(const uint4*)pAlo;
    uint4 rWh = *(const uint4*)pWhi;
    uint4 rWl = *(const uint4*)pWlo;
    {
        unsigned char* b0 = smem[0];
        *(uint4*)(b0 +         soff) = rAh;
        *(uint4*)(b0 +  5120 + soff) = rAl;
        *(uint4*)(b0 + 10240 + soff) = rWh;
        *(uint4*)(b0 + 15360 + soff) = rWl;
    }
    rAh = *(const uint4*)(pAhi + 32);
    rAl = *(const uint4*)(pAlo + 32);
    rWh = *(const uint4*)(pWhi + 32);
    rWl = *(const uint4*)(pWlo + 32);
    __syncthreads();

    for (int kc = 0; kc < 16; kc++) {
        unsigned char* cb = smem[kc & 1];

        if (kc < 15) {
            unsigned char* nb = smem[(kc & 1) ^ 1];
            *(uint4*)(nb +         soff) = rAh;
            *(uint4*)(nb +  5120 + soff) = rAl;
            *(uint4*)(nb + 10240 + soff) = rWh;
            *(uint4*)(nb + 15360 + soff) = rWl;
            if (kc < 14) {
                const int ko = (kc + 2) * 32;
                rAh = *(const uint4*)(pAhi + ko);
                rAl = *(const uint4*)(pAlo + ko);
                rWh = *(const uint4*)(pWhi + ko);
                rWl = *(const uint4*)(pWlo + ko);
            }
        }

#pragma unroll
        for (int ks = 0; ks < 2; ks++) {
            uint32_t aAddr = s2u(cb + aRow * 80 + ks * 32 + aByte);
            uint32_t ah0, ah1, ah2, ah3, al0, al1, al2, al3;
            LDSM4(ah0, ah1, ah2, ah3, aAddr);
            LDSM4(al0, al1, al2, al3, aAddr + 5120);

            uint32_t bAddrBase = s2u(cb + 10240 + bRow4 * 80 + ks * 32 + bByte4);
            uint32_t bh[8], bl[8];
#pragma unroll
            for (int jp = 0; jp < 2; jp++) {
                // rows advance by 16 per jpair -> 16*80 bytes
                uint32_t ba = bAddrBase + jp * (16 * 80);
                LDSM4(bh[jp*4+0], bh[jp*4+1], bh[jp*4+2], bh[jp*4+3], ba);
                LDSM4(bl[jp*4+0], bl[jp*4+1], bl[jp*4+2], bl[jp*4+3], ba + 5120);
            }

#pragma unroll
            for (int j = 0; j < 4; j++) {
                const uint32_t b0h = bh[j*2], b1h = bh[j*2+1];
                const uint32_t b0l = bl[j*2], b1l = bl[j*2+1];
                MMA16816(acc[j], ah0, ah1, ah2, ah3, b0h, b1h);
                MMA16816(acc[j], ah0, ah1, ah2, ah3, b0l, b1l);
                MMA16816(acc[j], al0, al1, al2, al3, b0h, b1h);
            }
        }
        __syncthreads();
    }

    // Epilogue: D frag -> C rows (row = wm*16 + lane/4 (+8)), cols (lane%4)*2.
    const int erow  = wm * 16 + (lane >> 2);
    const int ecol0 = wn * 32 + (lane & 3) * 2;
#pragma unroll
    for (int j = 0; j < 4; j++) {
        const int col = ecol0 + j * 8;
        float b0v = 0.f, b1v = 0.f;
        if (is_text) { b0v = bias[v0 + col]; b1v = bias[v0 + col + 1]; }
        float2 o0 = make_float2(acc[j][0] + b0v, acc[j][1] + b1v);
        float2 o1 = make_float2(acc[j][2] + b0v, acc[j][3] + b1v);
        *(float2*)(C + (size_t)erow * VV + v0 + col)       = o0;
        *(float2*)(C + (size_t)(erow + 8) * VV + v0 + col) = o1;
    }
}

// ---------------------------------------------------------------------------
// Kernel 2: broadcast add: out[bt, u, v] = sp[bt, v] + tp[b*U + u, v].
// 256 threads per block, block covers 2 bt rows; 2-u unroll for store MLP.
// ---------------------------------------------------------------------------
__global__ __launch_bounds__(256)
void bcast_add_kernel(float* __restrict__ out)
{
    const int tid = threadIdx.x;
    const int bt  = blockIdx.x * 2 + (tid >> 7);   // 0..2047
    const int b   = bt >> 9;                       // batch index
    const int v4  = tid & 127;                     // float4 column

    const float4* sp4 = (const float4*)g_sp;
    const float4* tp4 = (const float4*)g_tp;

    float4 s = sp4[(size_t)bt * 128 + v4];

    const float4* tprow = tp4 + (size_t)b * UU * 128 + v4;
    float4* ob = (float4*)out + (size_t)bt * UU * 128 + v4;

#pragma unroll 2
    for (int u = 0; u < UU; u += 2) {
        float4 t0 = tprow[(size_t)u * 128];
        float4 t1 = tprow[(size_t)(u + 1) * 128];
        float4 r0, r1;
        r0.x = s.x + t0.x; r0.y = s.y + t0.y;
        r0.z = s.z + t0.z; r0.w = s.w + t0.w;
        r1.x = s.x + t1.x; r1.y = s.y + t1.y;
        r1.z = s.z + t1.z; r1.w = s.w + t1.w;
        ob[(size_t)u * 128]       = r0;
        ob[(size_t)(u + 1) * 128] = r1;
    }
}

extern "C" void kernel_launch(void* const* d_in, const int* in_sizes, int n_in,
                              void* d_out, int out_size)
{
    const float* speech = (const float*)d_in[0];
    const float* text   = (const float*)d_in[1];
    const float* Wm     = (const float*)d_in[2];
    const float* bias   = (const float*)d_in[3];
    const int*   slen   = (const int*)d_in[4];
    const int*   tlen   = (const int*)d_in[5];

    // Phase 0: fp32 -> bf16 hi/lo split (+ length tail)
    convert_kernel<<<768, 256>>>(speech, text, Wm, slen, tlen, (float*)d_out);

    // Phase 1: tensor-core split GEMM (speech + text w/ bias)
    mma_gemm_kernel<<<320, 256>>>(bias);

    // Phase 2: broadcast add (DRAM-write-bound floor)
    bcast_add_kernel<<<MS / 2, 256>>>((float*)d_out);
}